// round 15
// baseline (speedup 1.0000x reference)
#include <cuda_runtime.h>
#include <cuda_fp16.h>
#include <math.h>
#include <cstdint>

#define TT 4096
#define HH 2048
#define EE 32
#define II 1024
#define TOPK 8
#define SIc 2048           // shared intermediate
#define NGU 2048           // 2*I
#define NGUS 4096          // 2*SI
#define TROWS (TT * TOPK)
#define PROWS (TROWS + 128)
#define MAXTILES 288       // sum ceil(cnt_e/128) <= 256 + 32

// ---------------- static device scratch ----------------
__device__ float g_logits[TT * EE];
__device__ int   g_cnt[EE];
__device__ int   g_rowOff[EE + 1];
__device__ int   g_tileOff[EE + 1];
__device__ int   g_slot_e[TT * TOPK];
__device__ int   g_slot_pos[TT * TOPK];
__device__ int   g_bucket_tok[EE * TT];
__device__ float g_bucket_w[EE * TT];

__device__ __align__(16) __half g_x_h[(size_t)TT * HH];          // 16 MB
__device__ __align__(16) __half g_h_r[(size_t)PROWS * II];       // 67 MB
__device__ __align__(16) __half g_h_s[(size_t)TT * SIc];         // 16.8 MB
__device__ __align__(16) __half g_y_h[(size_t)PROWS * HH];       // 134 MB (fp16 routed Y)

// ---------------- ptx helpers ----------------
__device__ __forceinline__ void cp16(unsigned dst, const void* src) {
    asm volatile("cp.async.cg.shared.global [%0], [%1], 16;\n" :: "r"(dst), "l"(src));
}
__device__ __forceinline__ void cp_commit() { asm volatile("cp.async.commit_group;\n"); }
template<int N> __device__ __forceinline__ void cp_wait() {
    asm volatile("cp.async.wait_group %0;\n" :: "n"(N));
}
__device__ __forceinline__ float silu_f(float g) {
    return g / (1.0f + __expf(-g));
}
__device__ __forceinline__ void ldsm4(unsigned addr, unsigned& r0, unsigned& r1,
                                      unsigned& r2, unsigned& r3) {
    asm volatile("ldmatrix.sync.aligned.m8n8.x4.shared.b16 {%0,%1,%2,%3}, [%4];"
        : "=r"(r0), "=r"(r1), "=r"(r2), "=r"(r3) : "r"(addr));
}
__device__ __forceinline__ void ldsm4t(unsigned addr, unsigned& r0, unsigned& r1,
                                       unsigned& r2, unsigned& r3) {
    asm volatile("ldmatrix.sync.aligned.m8n8.x4.trans.shared.b16 {%0,%1,%2,%3}, [%4];"
        : "=r"(r0), "=r"(r1), "=r"(r2), "=r"(r3) : "r"(addr));
}
__device__ __forceinline__ void mma16816(float* c, unsigned a0, unsigned a1,
                                         unsigned a2, unsigned a3,
                                         unsigned b0, unsigned b1) {
    asm volatile(
        "mma.sync.aligned.m16n8k16.row.col.f32.f16.f16.f32 "
        "{%0,%1,%2,%3}, {%4,%5,%6,%7}, {%8,%9}, {%0,%1,%2,%3};"
        : "+f"(c[0]), "+f"(c[1]), "+f"(c[2]), "+f"(c[3])
        : "r"(a0), "r"(a1), "r"(a2), "r"(a3), "r"(b0), "r"(b1));
}
__device__ __forceinline__ void sts16(unsigned addr, unsigned x, unsigned y,
                                      unsigned z, unsigned w) {
    asm volatile("st.shared.v4.b32 [%0], {%1,%2,%3,%4};"
        :: "r"(addr), "r"(x), "r"(y), "r"(z), "r"(w));
}

// ---------------- x fp32 -> fp16 convert ----------------
__global__ __launch_bounds__(256) void f2h_kernel(const float4* __restrict__ src,
                                                  __half* __restrict__ dst, long n4) {
    long stride = (long)gridDim.x * blockDim.x;
    for (long i = (long)blockIdx.x * blockDim.x + threadIdx.x; i < n4; i += stride) {
        float4 v = src[i];
        __half2 h0 = __floats2half2_rn(v.x, v.y);
        __half2 h1 = __floats2half2_rn(v.z, v.w);
        uint2 packed;
        packed.x = *(unsigned*)&h0;
        packed.y = *(unsigned*)&h1;
        *(uint2*)(dst + i * 4) = packed;
    }
}

// ---------------- small kernels ----------------
__global__ void zero_cnt_kernel() {
    if (threadIdx.x < EE) g_cnt[threadIdx.x] = 0;
}
__global__ void prefix_kernel() {
    if (threadIdx.x == 0) {
        int ro = 0, to = 0;
        for (int e = 0; e < EE; e++) {
            g_rowOff[e] = ro;
            g_tileOff[e] = to;
            ro += g_cnt[e];
            to += (g_cnt[e] + 127) >> 7;
        }
        g_rowOff[EE] = ro;
        g_tileOff[EE] = to;
    }
}

// ---------------- router GEMM ----------------
__global__ __launch_bounds__(256) void router_gemm_kernel(
    const float* __restrict__ x, const float* __restrict__ gw)
{
    __shared__ float As[64][33];
    __shared__ float Bs[64][33];
    int m0 = blockIdx.x * 32;
    int tid = threadIdx.x;
    int t2 = (tid & 15) * 2;
    int e2 = (tid >> 4) * 2;
    float a00 = 0.f, a01 = 0.f, a10 = 0.f, a11 = 0.f;

    for (int k0 = 0; k0 < HH; k0 += 64) {
        #pragma unroll
        for (int p = 0; p < 2; p++) {
            int idx = tid + p * 256;
            int r = idx >> 4;
            int c4 = (idx & 15) * 4;
            float4 v = *(const float4*)(x + (size_t)(m0 + r) * HH + k0 + c4);
            As[c4 + 0][r] = v.x; As[c4 + 1][r] = v.y;
            As[c4 + 2][r] = v.z; As[c4 + 3][r] = v.w;
        }
        #pragma unroll
        for (int p = 0; p < 2; p++) {
            int idx = tid + p * 256;
            int r = idx >> 3;
            int c4 = (idx & 7) * 4;
            float4 v = *(const float4*)(gw + (size_t)(k0 + r) * EE + c4);
            Bs[r][c4 + 0] = v.x; Bs[r][c4 + 1] = v.y;
            Bs[r][c4 + 2] = v.z; Bs[r][c4 + 3] = v.w;
        }
        __syncthreads();
        #pragma unroll 8
        for (int k = 0; k < 64; k++) {
            float x0 = As[k][t2], x1 = As[k][t2 + 1];
            float b0 = Bs[k][e2], b1 = Bs[k][e2 + 1];
            a00 += x0 * b0; a01 += x0 * b1;
            a10 += x1 * b0; a11 += x1 * b1;
        }
        __syncthreads();
    }
    g_logits[(size_t)(m0 + t2) * EE + e2]     = a00;
    g_logits[(size_t)(m0 + t2) * EE + e2 + 1] = a01;
    g_logits[(size_t)(m0 + t2 + 1) * EE + e2]     = a10;
    g_logits[(size_t)(m0 + t2 + 1) * EE + e2 + 1] = a11;
}

// ---------------- grouped top-k + bucketing ----------------
__global__ void topk_kernel(const float* __restrict__ bias) {
    int t = blockIdx.x * blockDim.x + threadIdx.x;
    if (t >= TT) return;

    float sco[EE], scb[EE];
    #pragma unroll
    for (int e = 0; e < EE; e++) {
        float l = g_logits[(size_t)t * EE + e];
        float s = 1.0f / (1.0f + expf(-l));
        sco[e] = s;
        scb[e] = s + bias[e];
    }
    float gs[8];
    #pragma unroll
    for (int g = 0; g < 8; g++) {
        int b = g * 4;
        float m1 = scb[b], m2 = -1e30f;
        #pragma unroll
        for (int i = 1; i < 4; i++) {
            float v = scb[b + i];
            if (v > m1) { m2 = m1; m1 = v; }
            else if (v > m2) { m2 = v; }
        }
        gs[g] = m1 + m2;
    }
    bool gsel[8];
    #pragma unroll
    for (int g = 0; g < 8; g++) gsel[g] = false;
    for (int it = 0; it < 4; it++) {
        float best = -1e30f; int bi = -1;
        #pragma unroll
        for (int g = 0; g < 8; g++)
            if (!gsel[g] && gs[g] > best) { best = gs[g]; bi = g; }
        gsel[bi] = true;
    }
    float msk[EE];
    #pragma unroll
    for (int e = 0; e < EE; e++) msk[e] = gsel[e >> 2] ? scb[e] : -1e30f;
    int ids[TOPK]; float ws[TOPK]; float wsum = 0.f;
    for (int it = 0; it < TOPK; it++) {
        float best = -1e30f; int bi = 0;
        #pragma unroll
        for (int e = 0; e < EE; e++)
            if (msk[e] > best) { best = msk[e]; bi = e; }
        msk[bi] = -1e30f;
        ids[it] = bi;
        ws[it] = sco[bi];
        wsum += ws[it];
    }
    float inv = 1.0f / (wsum + 1e-20f);
    #pragma unroll
    for (int k = 0; k < TOPK; k++) {
        int e = ids[k];
        float w = ws[k] * inv;
        int pos = atomicAdd(&g_cnt[e], 1);
        g_slot_e[t * TOPK + k] = e;
        g_slot_pos[t * TOPK + k] = pos;
        g_bucket_tok[e * TT + pos] = t;
        g_bucket_w[e * TT + pos] = w;
    }
}

// ---------------- main GEMM: 128x128x32, 3-stage; A via cp.async (fp16),
//                  B via LDG(fp32)->convert->STS software pipeline ----------------
// Grid: blockIdx.x = M-tile (fast), blockIdx.y = N-block
// EPI: 0 = fused pairwise silu(gate)*up -> half (B interleaved in-register from [gate|up] fp32)
//      1 = 2.5*w * D -> half y_h
//      2 = D -> float out (dense, no bounds)
#define ASZ 10240   // 128 rows * 40 halves * 2B (row pitch 80B)
#define BSZ 8704    // 32 rows * 136 halves * 2B (row pitch 272B)
#define STG (ASZ + BSZ)   // 18944
#define DYN_SMEM (3 * STG)

template<int EPI, bool ROUTED, bool GATHER>
__global__ __launch_bounds__(256, 2) void mm2_kernel(
    const __half* __restrict__ Ah, const float* __restrict__ Bf, size_t BexpStrideF,
    int srcN, int pairHalf, int K, int M_dense,
    __half* __restrict__ outH, int ldH, float* __restrict__ outF, int ldF)
{
    extern __shared__ __align__(16) char sm[];
    int tid = threadIdx.x;
    int wid = tid >> 5;
    int lane = tid & 31;

    int e = 0, m0, Mrows, rbase;
    const float* B = Bf;
    if (ROUTED) {
        int tlin = blockIdx.x;
        if (tlin >= g_tileOff[EE]) return;
        while (g_tileOff[e + 1] <= tlin) e++;
        m0 = (tlin - g_tileOff[e]) * 128;
        Mrows = g_cnt[e];
        B += (size_t)e * BexpStrideF;
        rbase = g_rowOff[e];
    } else {
        m0 = blockIdx.x * 128;
        Mrows = M_dense;
        rbase = 0;
    }
    int n0 = blockIdx.y * 128;

    unsigned smb = (unsigned)__cvta_generic_to_shared(sm);

    // A loads (fp16, cp.async): 2 per thread. row = tid>>2, col8 = tid&3
    int rA = tid >> 2;
    int cA = tid & 3;
    const __half* aptr[2];
    #pragma unroll
    for (int p = 0; p < 2; p++) {
        int r = rA + p * 64;
        size_t row;
        if (GATHER) {
            int ml = m0 + r;
            int tok = (ml < Mrows) ? g_bucket_tok[e * TT + ml] : 0;
            row = (size_t)tok;
        } else if (ROUTED) {
            row = (size_t)(rbase + m0 + r);
        } else {
            row = (size_t)(m0 + r);
        }
        aptr[p] = Ah + row * (size_t)K + cA * 8;
    }
    unsigned aDst[2];
    #pragma unroll
    for (int p = 0; p < 2; p++) aDst[p] = (rA + p * 64) * 80u + cA * 16u;

    // B fp32 loads: thread covers row rB2 = tid>>3 (0..31), 16 dst halves at (tid&7)*16
    int rB2 = tid >> 3;
    int cSeg = tid & 7;
    const float* bG;   // gate/plain pointer (4 float4 from here and +pairHalf for EPI0)
    if (EPI == 0) {
        bG = B + (size_t)rB2 * srcN + (n0 >> 1) + cSeg * 8;
    } else {
        bG = B + (size_t)rB2 * srcN + n0 + cSeg * 16;
    }
    long bStepF = (long)32 * srcN;   // floats per K-stage
    unsigned bDstByte = (unsigned)ASZ + rB2 * 272u + cSeg * 32u;

    int S = K >> 5;

    float4 hb0, hb1, hb2, hb3;   // held B regs for next stage

    // helper lambdas via macros (keep regs tight)
    #define LDG_B(sidx)                                                        \
        do {                                                                   \
            const float* p_ = bG + (long)(sidx) * bStepF;                      \
            if (EPI == 0) {                                                    \
                hb0 = *(const float4*)(p_);                                    \
                hb1 = *(const float4*)(p_ + 4);                                \
                hb2 = *(const float4*)(p_ + pairHalf);                         \
                hb3 = *(const float4*)(p_ + pairHalf + 4);                     \
            } else {                                                           \
                hb0 = *(const float4*)(p_);                                    \
                hb1 = *(const float4*)(p_ + 4);                                \
                hb2 = *(const float4*)(p_ + 8);                                \
                hb3 = *(const float4*)(p_ + 12);                               \
            }                                                                  \
        } while (0)

    #define STS_B(bufidx)                                                      \
        do {                                                                   \
            unsigned d_ = smb + (bufidx) * STG + bDstByte;                     \
            __half2 q0, q1, q2, q3, q4, q5, q6, q7;                            \
            if (EPI == 0) {                                                    \
                q0 = __floats2half2_rn(hb0.x, hb2.x);                          \
                q1 = __floats2half2_rn(hb0.y, hb2.y);                          \
                q2 = __floats2half2_rn(hb0.z, hb2.z);                          \
                q3 = __floats2half2_rn(hb0.w, hb2.w);                          \
                q4 = __floats2half2_rn(hb1.x, hb3.x);                          \
                q5 = __floats2half2_rn(hb1.y, hb3.y);                          \
                q6 = __floats2half2_rn(hb1.z, hb3.z);                          \
                q7 = __floats2half2_rn(hb1.w, hb3.w);                          \
            } else {                                                           \
                q0 = __floats2half2_rn(hb0.x, hb0.y);                          \
                q1 = __floats2half2_rn(hb0.z, hb0.w);                          \
                q2 = __floats2half2_rn(hb1.x, hb1.y);                          \
                q3 = __floats2half2_rn(hb1.z, hb1.w);                          \
                q4 = __floats2half2_rn(hb2.x, hb2.y);                          \
                q5 = __floats2half2_rn(hb2.z, hb2.w);                          \
                q6 = __floats2half2_rn(hb3.x, hb3.y);                          \
                q7 = __floats2half2_rn(hb3.z, hb3.w);                          \
            }                                                                  \
            sts16(d_, *(unsigned*)&q0, *(unsigned*)&q1,                        \
                  *(unsigned*)&q2, *(unsigned*)&q3);                           \
            sts16(d_ + 16, *(unsigned*)&q4, *(unsigned*)&q5,                   \
                  *(unsigned*)&q6, *(unsigned*)&q7);                           \
        } while (0)

    // prologue: B stage 0 (LDG + STS), B stage 1 (LDG, held); A stages 0,1 cp.async
    LDG_B(0);
    STS_B(0);
    if (S > 1) LDG_B(1);
    #pragma unroll
    for (int s = 0; s < 2; s++) {
        unsigned base = smb + s * STG;
        cp16(base + aDst[0], aptr[0] + s * 32);
        cp16(base + aDst[1], aptr[1] + s * 32);
        cp_commit();
    }

    int wm = wid & 1;
    int wn = wid >> 1;

    int lrow = (lane & 7) + ((lane >> 3) & 1) * 8;
    int lc16 = (lane >> 4) * 16;
    unsigned aLd = (unsigned)(lrow * 80 + lc16) + (unsigned)(wm * 64) * 80u;
    unsigned bLd = (unsigned)(lrow * 272 + lc16) + (unsigned)ASZ + (unsigned)(wn * 64);

    float acc[4][4][4];
    #pragma unroll
    for (int i = 0; i < 4; i++)
        #pragma unroll
        for (int j = 0; j < 4; j++)
            #pragma unroll
            for (int q = 0; q < 4; q++)
                acc[i][j][q] = 0.0f;

    int buf = 0;
    for (int s = 0; s < S; s++) {
        if (s == S - 1) cp_wait<0>(); else cp_wait<1>();
        __syncthreads();

        // STS held B for stage s+1 (buffer (s+1)%3, last read at step s-2)
        if (s + 1 < S) {
            int nb1 = buf + 1; if (nb1 >= 3) nb1 -= 3;
            STS_B(nb1);
        }
        // prefetch B for stage s+2 into regs
        if (s + 2 < S) LDG_B(s + 2);

        unsigned tbase = smb + buf * STG;
        #pragma unroll
        for (int ks = 0; ks < 2; ks++) {
            unsigned a[4][4];
            #pragma unroll
            for (int i = 0; i < 4; i++)
                ldsm4(tbase + aLd + ks * 32 + i * (16 * 80),
                      a[i][0], a[i][1], a[i][2], a[i][3]);
            unsigned b[2][4];
            #pragma unroll
            for (int p = 0; p < 2; p++)
                ldsm4t(tbase + bLd + ks * (16 * 272) + p * 32,
                       b[p][0], b[p][1], b[p][2], b[p][3]);
            #pragma unroll
            for (int i = 0; i < 4; i++)
                #pragma unroll
                for (int jc = 0; jc < 4; jc++)
                    mma16816(acc[i][jc],
                             a[i][0], a[i][1], a[i][2], a[i][3],
                             b[jc >> 1][(jc & 1) * 2], b[jc >> 1][(jc & 1) * 2 + 1]);
        }

        // A cp.async for stage s+2 (buffer (s+2)%3, last read at step s-1)
        if (s + 2 < S) {
            int nb = buf + 2; if (nb >= 3) nb -= 3;
            int k0 = (s + 2) * 32;
            unsigned base = smb + nb * STG;
            cp16(base + aDst[0], aptr[0] + k0);
            cp16(base + aDst[1], aptr[1] + k0);
            cp_commit();
        } else {
            cp_commit();  // keep group count consistent
        }
        buf++; if (buf >= 3) buf -= 3;
    }

    #undef LDG_B
    #undef STS_B

    // ---------------- register-direct epilogue ----------------
    int gr = lane >> 2;
    int gc = (lane & 3) * 2;

    if (EPI == 2) {
        #pragma unroll
        for (int i = 0; i < 4; i++) {
            int r0 = m0 + wm * 64 + i * 16 + gr;
            #pragma unroll
            for (int jc = 0; jc < 4; jc++) {
                int col = n0 + wn * 32 + jc * 8 + gc;
                *(float2*)(outF + (size_t)r0 * ldF + col) =
                    make_float2(acc[i][jc][0], acc[i][jc][1]);
                *(float2*)(outF + (size_t)(r0 + 8) * ldF + col) =
                    make_float2(acc[i][jc][2], acc[i][jc][3]);
            }
        }
    } else if (EPI == 0) {
        #pragma unroll
        for (int i = 0; i < 4; i++) {
            int ml0 = m0 + wm * 64 + i * 16 + gr;
            int ml1 = ml0 + 8;
            bool v0 = ml0 < Mrows, v1 = ml1 < Mrows;
            #pragma unroll
            for (int jc = 0; jc < 4; jc++) {
                int hcol = (n0 >> 1) + wn * 16 + jc * 4 + (lane & 3);
                if (v0)
                    outH[(size_t)(rbase + ml0) * ldH + hcol] =
                        __float2half_rn(silu_f(acc[i][jc][0]) * acc[i][jc][1]);
                if (v1)
                    outH[(size_t)(rbase + ml1) * ldH + hcol] =
                        __float2half_rn(silu_f(acc[i][jc][2]) * acc[i][jc][3]);
            }
        }
    } else {
        #pragma unroll
        for (int i = 0; i < 4; i++) {
            int ml0 = m0 + wm * 64 + i * 16 + gr;
            int ml1 = ml0 + 8;
            bool v0 = ml0 < Mrows, v1 = ml1 < Mrows;
            float s0 = v0 ? (2.5f * g_bucket_w[e * TT + ml0]) : 0.0f;
            float s1 = v1 ? (2.5f * g_bucket_w[e * TT + ml1]) : 0.0f;
            #pragma unroll
            for (int jc = 0; jc < 4; jc++) {
                int col = n0 + wn * 32 + jc * 8 + gc;
                if (v0) {
                    __half2 h = __floats2half2_rn(acc[i][jc][0] * s0, acc[i][jc][1] * s0);
                    *(__half2*)(outH + (size_t)(rbase + ml0) * ldH + col) = h;
                }
                if (v1) {
                    __half2 h = __floats2half2_rn(acc[i][jc][2] * s1, acc[i][jc][3] * s1);
                    *(__half2*)(outH + (size_t)(rbase + ml1) * ldH + col) = h;
                }
            }
        }
    }
}

// ---------------- combine: out[t] = shared[t] + sum_k y_h[row_k] ----------------
__global__ __launch_bounds__(256) void combine_kernel(float* __restrict__ out) {
    int t = blockIdx.x;
    int rows[TOPK];
    #pragma unroll
    for (int k = 0; k < TOPK; k++) {
        int e = g_slot_e[t * TOPK + k];
        rows[k] = g_rowOff[e] + g_slot_pos[t * TOPK + k];
    }
    int c = threadIdx.x * 4;
    #pragma unroll
    for (int rep = 0; rep < 2; rep++, c += 1024) {
        float4 s = *(float4*)(out + (size_t)t * HH + c);
        #pragma unroll
        for (int k = 0; k < TOPK; k++) {
            uint2 raw = *(const uint2*)(g_y_h + (size_t)rows[k] * HH + c);
            __half2 h0 = *(__half2*)&raw.x;
            __half2 h1 = *(__half2*)&raw.y;
            float2 f0 = __half22float2(h0);
            float2 f1 = __half22float2(h1);
            s.x += f0.x; s.y += f0.y; s.z += f1.x; s.w += f1.y;
        }
        *(float4*)(out + (size_t)t * HH + c) = s;
    }
}

// ---------------- launch ----------------
extern "C" void kernel_launch(void* const* d_in, const int* in_sizes, int n_in,
                              void* d_out, int out_size)
{
    const float* hidden = (const float*)d_in[0];
    const float* gate_w = (const float*)d_in[1];
    const float* gate_b = (const float*)d_in[2];
    const float* w_gu   = (const float*)d_in[3];
    const float* w_dn   = (const float*)d_in[4];
    const float* s_gu   = (const float*)d_in[5];
    const float* s_dn   = (const float*)d_in[6];
    float* out = (float*)d_out;

    __half *x_h, *h_r, *h_s, *y_h;
    cudaGetSymbolAddress((void**)&x_h, g_x_h);
    cudaGetSymbolAddress((void**)&h_r, g_h_r);
    cudaGetSymbolAddress((void**)&h_s, g_h_s);
    cudaGetSymbolAddress((void**)&y_h, g_y_h);

    cudaFuncSetAttribute(mm2_kernel<0, true,  true >, cudaFuncAttributeMaxDynamicSharedMemorySize, DYN_SMEM);
    cudaFuncSetAttribute(mm2_kernel<0, false, false>, cudaFuncAttributeMaxDynamicSharedMemorySize, DYN_SMEM);
    cudaFuncSetAttribute(mm2_kernel<1, true,  false>, cudaFuncAttributeMaxDynamicSharedMemorySize, DYN_SMEM);
    cudaFuncSetAttribute(mm2_kernel<2, false, false>, cudaFuncAttributeMaxDynamicSharedMemorySize, DYN_SMEM);

    // convert X only (weights consumed as fp32 directly by the GEMMs)
    f2h_kernel<<<1184, 256>>>((const float4*)hidden, x_h, (long)TT * HH / 4);

    zero_cnt_kernel<<<1, 32>>>();
    router_gemm_kernel<<<TT / 32, 256>>>(hidden, gate_w);
    topk_kernel<<<TT / 256, 256>>>(gate_b);
    prefix_kernel<<<1, 32>>>();

    // routed GEMM1 + fused act: h_r = silu_pair(gather(X) @ Wgu[e]), B fp32 [H][2I]
    mm2_kernel<0, true, true><<<dim3(MAXTILES, NGU / 128), 256, DYN_SMEM>>>(
        x_h, w_gu, (size_t)HH * NGU, NGU, II, HH, 0, h_r, II, nullptr, 0);

    // shared GEMM1 + fused act: h_s = silu_pair(X @ Sgu), B fp32 [H][2SI]
    mm2_kernel<0, false, false><<<dim3(TT / 128, NGUS / 128), 256, DYN_SMEM>>>(
        x_h, s_gu, 0, NGUS, SIc, HH, TT, h_s, SIc, nullptr, 0);

    // shared GEMM2: out = h_s @ Sdn, B fp32 [SI][H]
    mm2_kernel<2, false, false><<<dim3(TT / 128, HH / 128), 256, DYN_SMEM>>>(
        h_s, s_dn, 0, HH, 0, SIc, TT, nullptr, 0, out, HH);

    // routed GEMM2: y_h = 2.5*w * (h_r @ Wdn[e]), B fp32 [I][H]
    mm2_kernel<1, true, false><<<dim3(MAXTILES, HH / 128), 256, DYN_SMEM>>>(
        h_r, w_dn, (size_t)II * HH, HH, 0, II, 0, y_h, HH, nullptr, 0);

    // combine routed into d_out
    combine_kernel<<<TT, 256>>>(out);
}

// round 16
// speedup vs baseline: 1.1474x; 1.1474x over previous
#include <cuda_runtime.h>
#include <cuda_fp16.h>
#include <math.h>
#include <cstdint>

#define TT 4096
#define HH 2048
#define EE 32
#define II 1024
#define TOPK 8
#define SIc 2048           // shared intermediate
#define NGU 2048           // 2*I
#define NGUS 4096          // 2*SI
#define TROWS (TT * TOPK)
#define PROWS (TROWS + 128)
#define MAXTILES 288       // sum ceil(cnt_e/128) <= 256 + 32

// ---------------- static device scratch ----------------
__device__ float g_logits[TT * EE];
__device__ int   g_cnt[EE];
__device__ int   g_rowOff[EE + 1];
__device__ int   g_tileOff[EE + 1];
__device__ int   g_slot_e[TT * TOPK];
__device__ int   g_slot_pos[TT * TOPK];
__device__ int   g_bucket_tok[EE * TT];
__device__ float g_bucket_w[EE * TT];

__device__ __align__(16) __half g_x_h[(size_t)TT * HH];          // 16 MB
__device__ __align__(16) __half g_wgu_p[(size_t)EE * HH * NGU];  // paired gate/up, 268 MB
__device__ __align__(16) __half g_wdn_h[(size_t)EE * II * HH];   // 134 MB
__device__ __align__(16) __half g_sgu_p[(size_t)HH * NGUS];      // paired, 33.5 MB
__device__ __align__(16) __half g_sdn_h[(size_t)SIc * HH];       // 16.8 MB

__device__ __align__(16) __half g_h_r[(size_t)PROWS * II];       // 67 MB
__device__ __align__(16) __half g_h_s[(size_t)TT * SIc];         // 16.8 MB
__device__ __align__(16) __half g_y_h[(size_t)PROWS * HH];       // 134 MB (fp16 routed Y)

// ---------------- ptx helpers ----------------
__device__ __forceinline__ void cp16(unsigned dst, const void* src) {
    asm volatile("cp.async.cg.shared.global [%0], [%1], 16;\n" :: "r"(dst), "l"(src));
}
__device__ __forceinline__ void cp_commit() { asm volatile("cp.async.commit_group;\n"); }
template<int N> __device__ __forceinline__ void cp_wait() {
    asm volatile("cp.async.wait_group %0;\n" :: "n"(N));
}
__device__ __forceinline__ float silu_f(float g) {
    return g / (1.0f + __expf(-g));
}
__device__ __forceinline__ void ldsm4(unsigned addr, unsigned& r0, unsigned& r1,
                                      unsigned& r2, unsigned& r3) {
    asm volatile("ldmatrix.sync.aligned.m8n8.x4.shared.b16 {%0,%1,%2,%3}, [%4];"
        : "=r"(r0), "=r"(r1), "=r"(r2), "=r"(r3) : "r"(addr));
}
__device__ __forceinline__ void ldsm4t(unsigned addr, unsigned& r0, unsigned& r1,
                                       unsigned& r2, unsigned& r3) {
    asm volatile("ldmatrix.sync.aligned.m8n8.x4.trans.shared.b16 {%0,%1,%2,%3}, [%4];"
        : "=r"(r0), "=r"(r1), "=r"(r2), "=r"(r3) : "r"(addr));
}
__device__ __forceinline__ void mma16816(float* c, unsigned a0, unsigned a1,
                                         unsigned a2, unsigned a3,
                                         unsigned b0, unsigned b1) {
    asm volatile(
        "mma.sync.aligned.m16n8k16.row.col.f32.f16.f16.f32 "
        "{%0,%1,%2,%3}, {%4,%5,%6,%7}, {%8,%9}, {%0,%1,%2,%3};"
        : "+f"(c[0]), "+f"(c[1]), "+f"(c[2]), "+f"(c[3])
        : "r"(a0), "r"(a1), "r"(a2), "r"(a3), "r"(b0), "r"(b1));
}

// ---------------- weight prep kernels ----------------
__global__ __launch_bounds__(256) void f2h_kernel(const float4* __restrict__ src,
                                                  __half* __restrict__ dst, long n4) {
    long stride = (long)gridDim.x * blockDim.x;
    for (long i = (long)blockIdx.x * blockDim.x + threadIdx.x; i < n4; i += stride) {
        float4 v = src[i];
        __half2 h0 = __floats2half2_rn(v.x, v.y);
        __half2 h1 = __floats2half2_rn(v.z, v.w);
        uint2 packed;
        packed.x = *(unsigned*)&h0;
        packed.y = *(unsigned*)&h1;
        *(uint2*)(dst + i * 4) = packed;
    }
}

// pair-interleave: src row [gate | up] -> dst {g,u,g,u,...} fp16
__global__ __launch_bounds__(256) void pair_kernel(
    const float* __restrict__ src, __half* __restrict__ dst,
    long rows, int half)
{
    int q = half >> 2;
    long total = rows * (long)q;
    long stride = (long)gridDim.x * blockDim.x;
    for (long i = (long)blockIdx.x * blockDim.x + threadIdx.x; i < total; i += stride) {
        long r = i / q;
        int j = (int)(i - r * q);
        const float* sr = src + r * (long)(2 * half);
        float4 gv = *(const float4*)(sr + 4 * j);
        float4 uv = *(const float4*)(sr + half + 4 * j);
        __half2 p0 = __floats2half2_rn(gv.x, uv.x);
        __half2 p1 = __floats2half2_rn(gv.y, uv.y);
        __half2 p2 = __floats2half2_rn(gv.z, uv.z);
        __half2 p3 = __floats2half2_rn(gv.w, uv.w);
        uint4 o;
        o.x = *(unsigned*)&p0; o.y = *(unsigned*)&p1;
        o.z = *(unsigned*)&p2; o.w = *(unsigned*)&p3;
        *(uint4*)(dst + r * (long)(2 * half) + 8 * j) = o;
    }
}

// ---------------- small kernels ----------------
__global__ void zero_cnt_kernel() {
    if (threadIdx.x < EE) g_cnt[threadIdx.x] = 0;
}
__global__ void prefix_kernel() {
    if (threadIdx.x == 0) {
        int ro = 0, to = 0;
        for (int e = 0; e < EE; e++) {
            g_rowOff[e] = ro;
            g_tileOff[e] = to;
            ro += g_cnt[e];
            to += (g_cnt[e] + 127) >> 7;
        }
        g_rowOff[EE] = ro;
        g_tileOff[EE] = to;
    }
}

// ---------------- router GEMM ----------------
__global__ __launch_bounds__(256) void router_gemm_kernel(
    const float* __restrict__ x, const float* __restrict__ gw)
{
    __shared__ float As[64][33];
    __shared__ float Bs[64][33];
    int m0 = blockIdx.x * 32;
    int tid = threadIdx.x;
    int t2 = (tid & 15) * 2;
    int e2 = (tid >> 4) * 2;
    float a00 = 0.f, a01 = 0.f, a10 = 0.f, a11 = 0.f;

    for (int k0 = 0; k0 < HH; k0 += 64) {
        #pragma unroll
        for (int p = 0; p < 2; p++) {
            int idx = tid + p * 256;
            int r = idx >> 4;
            int c4 = (idx & 15) * 4;
            float4 v = *(const float4*)(x + (size_t)(m0 + r) * HH + k0 + c4);
            As[c4 + 0][r] = v.x; As[c4 + 1][r] = v.y;
            As[c4 + 2][r] = v.z; As[c4 + 3][r] = v.w;
        }
        #pragma unroll
        for (int p = 0; p < 2; p++) {
            int idx = tid + p * 256;
            int r = idx >> 3;
            int c4 = (idx & 7) * 4;
            float4 v = *(const float4*)(gw + (size_t)(k0 + r) * EE + c4);
            Bs[r][c4 + 0] = v.x; Bs[r][c4 + 1] = v.y;
            Bs[r][c4 + 2] = v.z; Bs[r][c4 + 3] = v.w;
        }
        __syncthreads();
        #pragma unroll 8
        for (int k = 0; k < 64; k++) {
            float x0 = As[k][t2], x1 = As[k][t2 + 1];
            float b0 = Bs[k][e2], b1 = Bs[k][e2 + 1];
            a00 += x0 * b0; a01 += x0 * b1;
            a10 += x1 * b0; a11 += x1 * b1;
        }
        __syncthreads();
    }
    g_logits[(size_t)(m0 + t2) * EE + e2]     = a00;
    g_logits[(size_t)(m0 + t2) * EE + e2 + 1] = a01;
    g_logits[(size_t)(m0 + t2 + 1) * EE + e2]     = a10;
    g_logits[(size_t)(m0 + t2 + 1) * EE + e2 + 1] = a11;
}

// ---------------- grouped top-k + bucketing ----------------
__global__ void topk_kernel(const float* __restrict__ bias) {
    int t = blockIdx.x * blockDim.x + threadIdx.x;
    if (t >= TT) return;

    float sco[EE], scb[EE];
    #pragma unroll
    for (int e = 0; e < EE; e++) {
        float l = g_logits[(size_t)t * EE + e];
        float s = 1.0f / (1.0f + expf(-l));
        sco[e] = s;
        scb[e] = s + bias[e];
    }
    float gs[8];
    #pragma unroll
    for (int g = 0; g < 8; g++) {
        int b = g * 4;
        float m1 = scb[b], m2 = -1e30f;
        #pragma unroll
        for (int i = 1; i < 4; i++) {
            float v = scb[b + i];
            if (v > m1) { m2 = m1; m1 = v; }
            else if (v > m2) { m2 = v; }
        }
        gs[g] = m1 + m2;
    }
    bool gsel[8];
    #pragma unroll
    for (int g = 0; g < 8; g++) gsel[g] = false;
    for (int it = 0; it < 4; it++) {
        float best = -1e30f; int bi = -1;
        #pragma unroll
        for (int g = 0; g < 8; g++)
            if (!gsel[g] && gs[g] > best) { best = gs[g]; bi = g; }
        gsel[bi] = true;
    }
    float msk[EE];
    #pragma unroll
    for (int e = 0; e < EE; e++) msk[e] = gsel[e >> 2] ? scb[e] : -1e30f;
    int ids[TOPK]; float ws[TOPK]; float wsum = 0.f;
    for (int it = 0; it < TOPK; it++) {
        float best = -1e30f; int bi = 0;
        #pragma unroll
        for (int e = 0; e < EE; e++)
            if (msk[e] > best) { best = msk[e]; bi = e; }
        msk[bi] = -1e30f;
        ids[it] = bi;
        ws[it] = sco[bi];
        wsum += ws[it];
    }
    float inv = 1.0f / (wsum + 1e-20f);
    #pragma unroll
    for (int k = 0; k < TOPK; k++) {
        int e = ids[k];
        float w = ws[k] * inv;
        int pos = atomicAdd(&g_cnt[e], 1);
        g_slot_e[t * TOPK + k] = e;
        g_slot_pos[t * TOPK + k] = pos;
        g_bucket_tok[e * TT + pos] = t;
        g_bucket_w[e * TT + pos] = w;
    }
}

// ---------------- main GEMM: 128x128x32, 3-stage cp.async, ldmatrix+mma ----------------
// Grid: blockIdx.x = M-tile (fast), blockIdx.y = N-block
// EPI: 0 = fused pairwise silu(gate)*up -> half   (B pre-interleaved)
//      1 = 2.5*w * D -> half y_h
//      2 = D + sum_k y_h[row_k] -> float out (dense; fused routed combine)
#define ASZ 10240   // 128 rows * 40 halves * 2B (row pitch 80B)
#define BSZ 8704    // 32 rows * 136 halves * 2B (row pitch 272B)
#define STG (ASZ + BSZ)   // 18944
#define DYN_SMEM (3 * STG)

template<int EPI, bool ROUTED, bool GATHER>
__global__ __launch_bounds__(256, 2) void mm2_kernel(
    const __half* __restrict__ Ah, const __half* __restrict__ B0, size_t Bstride,
    int K, int N, int M_dense,
    __half* __restrict__ outH, int ldH, float* __restrict__ outF, int ldF)
{
    extern __shared__ __align__(16) char sm[];
    int tid = threadIdx.x;
    int wid = tid >> 5;
    int lane = tid & 31;

    int e = 0, m0, Mrows, rbase;
    const __half* B = B0;
    if (ROUTED) {
        int tlin = blockIdx.x;
        if (tlin >= g_tileOff[EE]) return;
        while (g_tileOff[e + 1] <= tlin) e++;
        m0 = (tlin - g_tileOff[e]) * 128;
        Mrows = g_cnt[e];
        B += (size_t)e * Bstride;
        rbase = g_rowOff[e];
    } else {
        m0 = blockIdx.x * 128;
        Mrows = M_dense;
        rbase = 0;
    }
    int n0 = blockIdx.y * 128;

    unsigned smb = (unsigned)__cvta_generic_to_shared(sm);

    // A loads: 2 per thread. op o = tid + p*256: row = o>>2 (0..127), col8 = (o&3)
    int rA = tid >> 2;
    int cA = tid & 3;
    const __half* aptr[2];
    #pragma unroll
    for (int p = 0; p < 2; p++) {
        int r = rA + p * 64;
        size_t row;
        if (GATHER) {
            int ml = m0 + r;
            int tok = (ml < Mrows) ? g_bucket_tok[e * TT + ml] : 0;
            row = (size_t)tok;
        } else if (ROUTED) {
            row = (size_t)(rbase + m0 + r);
        } else {
            row = (size_t)(m0 + r);
        }
        aptr[p] = Ah + row * (size_t)K + cA * 8;
    }
    unsigned aDst[2];
    #pragma unroll
    for (int p = 0; p < 2; p++) aDst[p] = (rA + p * 64) * 80u + cA * 16u;

    // B loads: 2 per thread. op o = tid + p*256: row = o>>4 (0..31), col8 = (o&15)
    int rB = tid >> 4;
    int cB = tid & 15;
    const __half* bptr = B + (size_t)rB * N + n0 + cB * 8;
    long bStep = (long)32 * N;
    unsigned bDst[2];
    #pragma unroll
    for (int p = 0; p < 2; p++) bDst[p] = (unsigned)ASZ + (rB + p * 16) * 272u + cB * 16u;
    long bOff2 = (long)16 * N;   // second half of B tile rows

    int S = K >> 5;

    // prologue: stages 0, 1
    #pragma unroll
    for (int s = 0; s < 2; s++) {
        unsigned base = smb + s * STG;
        cp16(base + aDst[0], aptr[0] + s * 32);
        cp16(base + aDst[1], aptr[1] + s * 32);
        cp16(base + bDst[0], bptr + s * bStep);
        cp16(base + bDst[1], bptr + s * bStep + bOff2);
        cp_commit();
    }

    int wm = wid & 1;
    int wn = wid >> 1;

    // per-lane ldmatrix offsets
    int lrow = (lane & 7) + ((lane >> 3) & 1) * 8;   // row within 16
    int lc16 = (lane >> 4) * 16;                      // 0 or 16 bytes
    unsigned aLd = (unsigned)(lrow * 80 + lc16) + (unsigned)(wm * 64) * 80u;
    unsigned bLd = (unsigned)(lrow * 272 + lc16) + (unsigned)ASZ + (unsigned)(wn * 64);

    float acc[4][4][4];
    #pragma unroll
    for (int i = 0; i < 4; i++)
        #pragma unroll
        for (int j = 0; j < 4; j++)
            #pragma unroll
            for (int q = 0; q < 4; q++)
                acc[i][j][q] = 0.0f;

    int buf = 0;
    for (int s = 0; s < S; s++) {
        if (s == S - 1) cp_wait<0>(); else cp_wait<1>();
        __syncthreads();

        unsigned tbase = smb + buf * STG;
        #pragma unroll
        for (int ks = 0; ks < 2; ks++) {
            unsigned a[4][4];
            #pragma unroll
            for (int i = 0; i < 4; i++)
                ldsm4(tbase + aLd + ks * 32 + i * (16 * 80),
                      a[i][0], a[i][1], a[i][2], a[i][3]);
            unsigned b[2][4];
            #pragma unroll
            for (int p = 0; p < 2; p++)
                ldsm4t(tbase + bLd + ks * (16 * 272) + p * 32,
                       b[p][0], b[p][1], b[p][2], b[p][3]);
            #pragma unroll
            for (int i = 0; i < 4; i++)
                #pragma unroll
                for (int jc = 0; jc < 4; jc++)
                    mma16816(acc[i][jc],
                             a[i][0], a[i][1], a[i][2], a[i][3],
                             b[jc >> 1][(jc & 1) * 2], b[jc >> 1][(jc & 1) * 2 + 1]);
        }

        if (s + 2 < S) {
            int nb = buf + 2; if (nb >= 3) nb -= 3;
            int k0 = (s + 2) * 32;
            unsigned base = smb + nb * STG;
            cp16(base + aDst[0], aptr[0] + k0);
            cp16(base + aDst[1], aptr[1] + k0);
            cp16(base + bDst[0], bptr + (long)(s + 2) * bStep);
            cp16(base + bDst[1], bptr + (long)(s + 2) * bStep + bOff2);
            cp_commit();
        }
        buf++; if (buf >= 3) buf -= 3;
    }

    // ---------------- register-direct epilogue ----------------
    int gr = lane >> 2;          // 0..7
    int gc = (lane & 3) * 2;     // 0,2,4,6

    if (EPI == 2) {
        // dense shared-GEMM2 tile + fused routed combine:
        // out[t][col] = acc + sum_k y_h[row_k(t)][col]
        #pragma unroll
        for (int i = 0; i < 4; i++) {
            int t0 = m0 + wm * 64 + i * 16 + gr;
            int t1 = t0 + 8;
            int rows0[TOPK], rows1[TOPK];
            #pragma unroll
            for (int k = 0; k < TOPK; k++) {
                int e0 = g_slot_e[t0 * TOPK + k];
                rows0[k] = g_rowOff[e0] + g_slot_pos[t0 * TOPK + k];
                int e1 = g_slot_e[t1 * TOPK + k];
                rows1[k] = g_rowOff[e1] + g_slot_pos[t1 * TOPK + k];
            }
            #pragma unroll
            for (int jc = 0; jc < 4; jc++) {
                int col = n0 + wn * 32 + jc * 8 + gc;
                float2 v0 = make_float2(acc[i][jc][0], acc[i][jc][1]);
                float2 v1 = make_float2(acc[i][jc][2], acc[i][jc][3]);
                #pragma unroll
                for (int k = 0; k < TOPK; k++) {
                    __half2 h0 = *(const __half2*)(g_y_h + (size_t)rows0[k] * HH + col);
                    float2 f0 = __half22float2(h0);
                    v0.x += f0.x; v0.y += f0.y;
                    __half2 h1 = *(const __half2*)(g_y_h + (size_t)rows1[k] * HH + col);
                    float2 f1 = __half22float2(h1);
                    v1.x += f1.x; v1.y += f1.y;
                }
                *(float2*)(outF + (size_t)t0 * ldF + col) = v0;
                *(float2*)(outF + (size_t)t1 * ldF + col) = v1;
            }
        }
    } else if (EPI == 0) {
        #pragma unroll
        for (int i = 0; i < 4; i++) {
            int ml0 = m0 + wm * 64 + i * 16 + gr;
            int ml1 = ml0 + 8;
            bool v0 = ml0 < Mrows, v1 = ml1 < Mrows;
            #pragma unroll
            for (int jc = 0; jc < 4; jc++) {
                int hcol = (n0 >> 1) + wn * 16 + jc * 4 + (lane & 3);
                if (v0)
                    outH[(size_t)(rbase + ml0) * ldH + hcol] =
                        __float2half_rn(silu_f(acc[i][jc][0]) * acc[i][jc][1]);
                if (v1)
                    outH[(size_t)(rbase + ml1) * ldH + hcol] =
                        __float2half_rn(silu_f(acc[i][jc][2]) * acc[i][jc][3]);
            }
        }
    } else {
        #pragma unroll
        for (int i = 0; i < 4; i++) {
            int ml0 = m0 + wm * 64 + i * 16 + gr;
            int ml1 = ml0 + 8;
            bool v0 = ml0 < Mrows, v1 = ml1 < Mrows;
            float s0 = v0 ? (2.5f * g_bucket_w[e * TT + ml0]) : 0.0f;
            float s1 = v1 ? (2.5f * g_bucket_w[e * TT + ml1]) : 0.0f;
            #pragma unroll
            for (int jc = 0; jc < 4; jc++) {
                int col = n0 + wn * 32 + jc * 8 + gc;
                if (v0) {
                    __half2 h = __floats2half2_rn(acc[i][jc][0] * s0, acc[i][jc][1] * s0);
                    *(__half2*)(outH + (size_t)(rbase + ml0) * ldH + col) = h;
                }
                if (v1) {
                    __half2 h = __floats2half2_rn(acc[i][jc][2] * s1, acc[i][jc][3] * s1);
                    *(__half2*)(outH + (size_t)(rbase + ml1) * ldH + col) = h;
                }
            }
        }
    }
}

// ---------------- launch ----------------
extern "C" void kernel_launch(void* const* d_in, const int* in_sizes, int n_in,
                              void* d_out, int out_size)
{
    const float* hidden = (const float*)d_in[0];
    const float* gate_w = (const float*)d_in[1];
    const float* gate_b = (const float*)d_in[2];
    const float* w_gu   = (const float*)d_in[3];
    const float* w_dn   = (const float*)d_in[4];
    const float* s_gu   = (const float*)d_in[5];
    const float* s_dn   = (const float*)d_in[6];
    float* out = (float*)d_out;

    __half *x_h, *wgu_p, *wdn_h, *sgu_p, *sdn_h, *h_r, *h_s, *y_h;
    cudaGetSymbolAddress((void**)&x_h,   g_x_h);
    cudaGetSymbolAddress((void**)&wgu_p, g_wgu_p);
    cudaGetSymbolAddress((void**)&wdn_h, g_wdn_h);
    cudaGetSymbolAddress((void**)&sgu_p, g_sgu_p);
    cudaGetSymbolAddress((void**)&sdn_h, g_sdn_h);
    cudaGetSymbolAddress((void**)&h_r,   g_h_r);
    cudaGetSymbolAddress((void**)&h_s,   g_h_s);
    cudaGetSymbolAddress((void**)&y_h,   g_y_h);

    cudaFuncSetAttribute(mm2_kernel<0, true,  true >, cudaFuncAttributeMaxDynamicSharedMemorySize, DYN_SMEM);
    cudaFuncSetAttribute(mm2_kernel<0, false, false>, cudaFuncAttributeMaxDynamicSharedMemorySize, DYN_SMEM);
    cudaFuncSetAttribute(mm2_kernel<1, true,  false>, cudaFuncAttributeMaxDynamicSharedMemorySize, DYN_SMEM);
    cudaFuncSetAttribute(mm2_kernel<2, false, false>, cudaFuncAttributeMaxDynamicSharedMemorySize, DYN_SMEM);

    const int CB = 1184;
    f2h_kernel<<<CB, 256>>>((const float4*)hidden, x_h,   (long)TT * HH / 4);
    pair_kernel<<<CB, 256>>>(w_gu, wgu_p, (long)EE * HH, II);
    pair_kernel<<<CB, 256>>>(s_gu, sgu_p, (long)HH, SIc);
    f2h_kernel<<<CB, 256>>>((const float4*)w_dn, wdn_h, (long)EE * II * HH / 4);
    f2h_kernel<<<CB, 256>>>((const float4*)s_dn, sdn_h, (long)SIc * HH / 4);

    zero_cnt_kernel<<<1, 32>>>();
    router_gemm_kernel<<<TT / 32, 256>>>(hidden, gate_w);
    topk_kernel<<<TT / 256, 256>>>(gate_b);
    prefix_kernel<<<1, 32>>>();

    // routed GEMM1 + fused act: h_r = silu_pair(gather(X) @ Wgu_p[e])
    mm2_kernel<0, true, true><<<dim3(MAXTILES, NGU / 128), 256, DYN_SMEM>>>(
        x_h, wgu_p, (size_t)HH * NGU, HH, NGU, 0, h_r, II, nullptr, 0);

    // shared GEMM1 + fused act: h_s = silu_pair(X @ Sgu_p)
    mm2_kernel<0, false, false><<<dim3(TT / 128, NGUS / 128), 256, DYN_SMEM>>>(
        x_h, sgu_p, 0, HH, NGUS, TT, h_s, SIc, nullptr, 0);

    // routed GEMM2 FIRST: y_h = 2.5*w * (h_r @ Wdn[e])  (fp16 half2 stores)
    mm2_kernel<1, true, false><<<dim3(MAXTILES, HH / 128), 256, DYN_SMEM>>>(
        h_r, wdn_h, (size_t)II * HH, II, HH, 0, y_h, HH, nullptr, 0);

    // shared GEMM2 + fused combine: out = h_s @ Sdn + sum_k y_h (writes all of d_out)
    mm2_kernel<2, false, false><<<dim3(TT / 128, HH / 128), 256, DYN_SMEM>>>(
        h_s, sdn_h, 0, SIc, HH, TT, nullptr, 0, out, HH);
}

// round 17
// speedup vs baseline: 1.1542x; 1.0060x over previous
#include <cuda_runtime.h>
#include <cuda_fp16.h>
#include <math.h>
#include <cstdint>

#define TT 4096
#define HH 2048
#define EE 32
#define II 1024
#define TOPK 8
#define SIc 2048           // shared intermediate
#define NGU 2048           // 2*I
#define NGUS 4096          // 2*SI
#define TROWS (TT * TOPK)
#define PROWS (TROWS + 128)
#define MAXTILES 288       // sum ceil(cnt_e/128) <= 256 + 32

// ---------------- static device scratch ----------------
__device__ float g_logits[TT * EE];
__device__ int   g_cnt[EE];
__device__ int   g_rowOff[EE + 1];
__device__ int   g_tileOff[EE + 1];
__device__ int   g_slot_e[TT * TOPK];
__device__ int   g_slot_pos[TT * TOPK];
__device__ int   g_bucket_tok[EE * TT];
__device__ float g_bucket_w[EE * TT];

__device__ __align__(16) __half g_x_h[(size_t)TT * HH];          // 16 MB
__device__ __align__(16) __half g_wgu_p[(size_t)EE * HH * NGU];  // paired gate/up, 268 MB
__device__ __align__(16) __half g_wdn_h[(size_t)EE * II * HH];   // 134 MB
__device__ __align__(16) __half g_sgu_p[(size_t)HH * NGUS];      // paired, 33.5 MB
__device__ __align__(16) __half g_sdn_h[(size_t)SIc * HH];       // 16.8 MB

__device__ __align__(16) __half g_h_r[(size_t)PROWS * II];       // 67 MB
__device__ __align__(16) __half g_h_s[(size_t)TT * SIc];         // 16.8 MB
__device__ __align__(16) __half g_y_h[(size_t)PROWS * HH];       // 134 MB (fp16 routed Y)

// ---------------- ptx helpers ----------------
__device__ __forceinline__ void cp16(unsigned dst, const void* src) {
    asm volatile("cp.async.cg.shared.global [%0], [%1], 16;\n" :: "r"(dst), "l"(src));
}
__device__ __forceinline__ void cp_commit() { asm volatile("cp.async.commit_group;\n"); }
template<int N> __device__ __forceinline__ void cp_wait() {
    asm volatile("cp.async.wait_group %0;\n" :: "n"(N));
}
__device__ __forceinline__ float silu_f(float g) {
    return g / (1.0f + __expf(-g));
}
__device__ __forceinline__ void ldsm4(unsigned addr, unsigned& r0, unsigned& r1,
                                      unsigned& r2, unsigned& r3) {
    asm volatile("ldmatrix.sync.aligned.m8n8.x4.shared.b16 {%0,%1,%2,%3}, [%4];"
        : "=r"(r0), "=r"(r1), "=r"(r2), "=r"(r3) : "r"(addr));
}
__device__ __forceinline__ void ldsm4t(unsigned addr, unsigned& r0, unsigned& r1,
                                       unsigned& r2, unsigned& r3) {
    asm volatile("ldmatrix.sync.aligned.m8n8.x4.trans.shared.b16 {%0,%1,%2,%3}, [%4];"
        : "=r"(r0), "=r"(r1), "=r"(r2), "=r"(r3) : "r"(addr));
}
__device__ __forceinline__ void mma16816(float* c, unsigned a0, unsigned a1,
                                         unsigned a2, unsigned a3,
                                         unsigned b0, unsigned b1) {
    asm volatile(
        "mma.sync.aligned.m16n8k16.row.col.f32.f16.f16.f32 "
        "{%0,%1,%2,%3}, {%4,%5,%6,%7}, {%8,%9}, {%0,%1,%2,%3};"
        : "+f"(c[0]), "+f"(c[1]), "+f"(c[2]), "+f"(c[3])
        : "r"(a0), "r"(a1), "r"(a2), "r"(a3), "r"(b0), "r"(b1));
}

// ---------------- weight prep kernels ----------------
__global__ __launch_bounds__(256) void f2h_kernel(const float4* __restrict__ src,
                                                  __half* __restrict__ dst, long n4) {
    long stride = (long)gridDim.x * blockDim.x;
    for (long i = (long)blockIdx.x * blockDim.x + threadIdx.x; i < n4; i += stride) {
        float4 v = src[i];
        __half2 h0 = __floats2half2_rn(v.x, v.y);
        __half2 h1 = __floats2half2_rn(v.z, v.w);
        uint2 packed;
        packed.x = *(unsigned*)&h0;
        packed.y = *(unsigned*)&h1;
        *(uint2*)(dst + i * 4) = packed;
    }
}

// pair-interleave: src row [gate | up] -> dst {g,u,g,u,...} fp16
__global__ __launch_bounds__(256) void pair_kernel(
    const float* __restrict__ src, __half* __restrict__ dst,
    long rows, int half)
{
    int q = half >> 2;
    long total = rows * (long)q;
    long stride = (long)gridDim.x * blockDim.x;
    for (long i = (long)blockIdx.x * blockDim.x + threadIdx.x; i < total; i += stride) {
        long r = i / q;
        int j = (int)(i - r * q);
        const float* sr = src + r * (long)(2 * half);
        float4 gv = *(const float4*)(sr + 4 * j);
        float4 uv = *(const float4*)(sr + half + 4 * j);
        __half2 p0 = __floats2half2_rn(gv.x, uv.x);
        __half2 p1 = __floats2half2_rn(gv.y, uv.y);
        __half2 p2 = __floats2half2_rn(gv.z, uv.z);
        __half2 p3 = __floats2half2_rn(gv.w, uv.w);
        uint4 o;
        o.x = *(unsigned*)&p0; o.y = *(unsigned*)&p1;
        o.z = *(unsigned*)&p2; o.w = *(unsigned*)&p3;
        *(uint4*)(dst + r * (long)(2 * half) + 8 * j) = o;
    }
}

// ---------------- small kernels ----------------
__global__ void prefix_kernel() {
    if (threadIdx.x == 0) {
        int ro = 0, to = 0;
        for (int e = 0; e < EE; e++) {
            g_rowOff[e] = ro;
            g_tileOff[e] = to;
            ro += g_cnt[e];
            to += (g_cnt[e] + 127) >> 7;
        }
        g_rowOff[EE] = ro;
        g_tileOff[EE] = to;
    }
}

// ---------------- router GEMM (also zeroes g_cnt from block 0) ----------------
__global__ __launch_bounds__(256) void router_gemm_kernel(
    const float* __restrict__ x, const float* __restrict__ gw)
{
    if (blockIdx.x == 0 && threadIdx.x < EE) g_cnt[threadIdx.x] = 0;

    __shared__ float As[64][33];
    __shared__ float Bs[64][33];
    int m0 = blockIdx.x * 32;
    int tid = threadIdx.x;
    int t2 = (tid & 15) * 2;
    int e2 = (tid >> 4) * 2;
    float a00 = 0.f, a01 = 0.f, a10 = 0.f, a11 = 0.f;

    for (int k0 = 0; k0 < HH; k0 += 64) {
        #pragma unroll
        for (int p = 0; p < 2; p++) {
            int idx = tid + p * 256;
            int r = idx >> 4;
            int c4 = (idx & 15) * 4;
            float4 v = *(const float4*)(x + (size_t)(m0 + r) * HH + k0 + c4);
            As[c4 + 0][r] = v.x; As[c4 + 1][r] = v.y;
            As[c4 + 2][r] = v.z; As[c4 + 3][r] = v.w;
        }
        #pragma unroll
        for (int p = 0; p < 2; p++) {
            int idx = tid + p * 256;
            int r = idx >> 3;
            int c4 = (idx & 7) * 4;
            float4 v = *(const float4*)(gw + (size_t)(k0 + r) * EE + c4);
            Bs[r][c4 + 0] = v.x; Bs[r][c4 + 1] = v.y;
            Bs[r][c4 + 2] = v.z; Bs[r][c4 + 3] = v.w;
        }
        __syncthreads();
        #pragma unroll 8
        for (int k = 0; k < 64; k++) {
            float x0 = As[k][t2], x1 = As[k][t2 + 1];
            float b0 = Bs[k][e2], b1 = Bs[k][e2 + 1];
            a00 += x0 * b0; a01 += x0 * b1;
            a10 += x1 * b0; a11 += x1 * b1;
        }
        __syncthreads();
    }
    g_logits[(size_t)(m0 + t2) * EE + e2]     = a00;
    g_logits[(size_t)(m0 + t2) * EE + e2 + 1] = a01;
    g_logits[(size_t)(m0 + t2 + 1) * EE + e2]     = a10;
    g_logits[(size_t)(m0 + t2 + 1) * EE + e2 + 1] = a11;
}

// ---------------- grouped top-k + bucketing (64-thr blocks for occupancy) ----------------
__global__ __launch_bounds__(64) void topk_kernel(const float* __restrict__ bias) {
    int t = blockIdx.x * blockDim.x + threadIdx.x;
    if (t >= TT) return;

    float sco[EE], scb[EE];
    #pragma unroll
    for (int e = 0; e < EE; e++) {
        float l = g_logits[(size_t)t * EE + e];
        float s = 1.0f / (1.0f + expf(-l));
        sco[e] = s;
        scb[e] = s + bias[e];
    }
    float gs[8];
    #pragma unroll
    for (int g = 0; g < 8; g++) {
        int b = g * 4;
        float m1 = scb[b], m2 = -1e30f;
        #pragma unroll
        for (int i = 1; i < 4; i++) {
            float v = scb[b + i];
            if (v > m1) { m2 = m1; m1 = v; }
            else if (v > m2) { m2 = v; }
        }
        gs[g] = m1 + m2;
    }
    bool gsel[8];
    #pragma unroll
    for (int g = 0; g < 8; g++) gsel[g] = false;
    for (int it = 0; it < 4; it++) {
        float best = -1e30f; int bi = -1;
        #pragma unroll
        for (int g = 0; g < 8; g++)
            if (!gsel[g] && gs[g] > best) { best = gs[g]; bi = g; }
        gsel[bi] = true;
    }
    float msk[EE];
    #pragma unroll
    for (int e = 0; e < EE; e++) msk[e] = gsel[e >> 2] ? scb[e] : -1e30f;
    int ids[TOPK]; float ws[TOPK]; float wsum = 0.f;
    for (int it = 0; it < TOPK; it++) {
        float best = -1e30f; int bi = 0;
        #pragma unroll
        for (int e = 0; e < EE; e++)
            if (msk[e] > best) { best = msk[e]; bi = e; }
        msk[bi] = -1e30f;
        ids[it] = bi;
        ws[it] = sco[bi];
        wsum += ws[it];
    }
    float inv = 1.0f / (wsum + 1e-20f);
    #pragma unroll
    for (int k = 0; k < TOPK; k++) {
        int e = ids[k];
        float w = ws[k] * inv;
        int pos = atomicAdd(&g_cnt[e], 1);
        g_slot_e[t * TOPK + k] = e;
        g_slot_pos[t * TOPK + k] = pos;
        g_bucket_tok[e * TT + pos] = t;
        g_bucket_w[e * TT + pos] = w;
    }
}

// ---------------- main GEMM: 128x128x32, 3-stage cp.async, ldmatrix+mma ----------------
// Grid: blockIdx.x = M-tile (fast), blockIdx.y = N-block
// EPI: 0 = fused pairwise silu(gate)*up -> half   (B pre-interleaved)
//      1 = 2.5*w * D -> half y_h
//      2 = D -> float out (dense, no bounds)
#define ASZ 10240   // 128 rows * 40 halves * 2B (row pitch 80B)
#define BSZ 8704    // 32 rows * 136 halves * 2B (row pitch 272B)
#define STG (ASZ + BSZ)   // 18944
#define DYN_SMEM (3 * STG)

template<int EPI, bool ROUTED, bool GATHER>
__global__ __launch_bounds__(256, 2) void mm2_kernel(
    const __half* __restrict__ Ah, const __half* __restrict__ B0, size_t Bstride,
    int K, int N, int M_dense,
    __half* __restrict__ outH, int ldH, float* __restrict__ outF, int ldF)
{
    extern __shared__ __align__(16) char sm[];
    int tid = threadIdx.x;
    int wid = tid >> 5;
    int lane = tid & 31;

    int e = 0, m0, Mrows, rbase;
    const __half* B = B0;
    if (ROUTED) {
        int tlin = blockIdx.x;
        if (tlin >= g_tileOff[EE]) return;
        while (g_tileOff[e + 1] <= tlin) e++;
        m0 = (tlin - g_tileOff[e]) * 128;
        Mrows = g_cnt[e];
        B += (size_t)e * Bstride;
        rbase = g_rowOff[e];
    } else {
        m0 = blockIdx.x * 128;
        Mrows = M_dense;
        rbase = 0;
    }
    int n0 = blockIdx.y * 128;

    unsigned smb = (unsigned)__cvta_generic_to_shared(sm);

    // A loads: 2 per thread. op o = tid + p*256: row = o>>2 (0..127), col8 = (o&3)
    int rA = tid >> 2;
    int cA = tid & 3;
    const __half* aptr[2];
    #pragma unroll
    for (int p = 0; p < 2; p++) {
        int r = rA + p * 64;
        size_t row;
        if (GATHER) {
            int ml = m0 + r;
            int tok = (ml < Mrows) ? g_bucket_tok[e * TT + ml] : 0;
            row = (size_t)tok;
        } else if (ROUTED) {
            row = (size_t)(rbase + m0 + r);
        } else {
            row = (size_t)(m0 + r);
        }
        aptr[p] = Ah + row * (size_t)K + cA * 8;
    }
    unsigned aDst[2];
    #pragma unroll
    for (int p = 0; p < 2; p++) aDst[p] = (rA + p * 64) * 80u + cA * 16u;

    // B loads: 2 per thread. op o = tid + p*256: row = o>>4 (0..31), col8 = (o&15)
    int rB = tid >> 4;
    int cB = tid & 15;
    const __half* bptr = B + (size_t)rB * N + n0 + cB * 8;
    long bStep = (long)32 * N;
    unsigned bDst[2];
    #pragma unroll
    for (int p = 0; p < 2; p++) bDst[p] = (unsigned)ASZ + (rB + p * 16) * 272u + cB * 16u;
    long bOff2 = (long)16 * N;   // second half of B tile rows

    int S = K >> 5;

    // prologue: stages 0, 1
    #pragma unroll
    for (int s = 0; s < 2; s++) {
        unsigned base = smb + s * STG;
        cp16(base + aDst[0], aptr[0] + s * 32);
        cp16(base + aDst[1], aptr[1] + s * 32);
        cp16(base + bDst[0], bptr + s * bStep);
        cp16(base + bDst[1], bptr + s * bStep + bOff2);
        cp_commit();
    }

    int wm = wid & 1;
    int wn = wid >> 1;

    // per-lane ldmatrix offsets
    int lrow = (lane & 7) + ((lane >> 3) & 1) * 8;   // row within 16
    int lc16 = (lane >> 4) * 16;                      // 0 or 16 bytes
    unsigned aLd = (unsigned)(lrow * 80 + lc16) + (unsigned)(wm * 64) * 80u;
    unsigned bLd = (unsigned)(lrow * 272 + lc16) + (unsigned)ASZ + (unsigned)(wn * 64);

    float acc[4][4][4];
    #pragma unroll
    for (int i = 0; i < 4; i++)
        #pragma unroll
        for (int j = 0; j < 4; j++)
            #pragma unroll
            for (int q = 0; q < 4; q++)
                acc[i][j][q] = 0.0f;

    int buf = 0;
    for (int s = 0; s < S; s++) {
        if (s == S - 1) cp_wait<0>(); else cp_wait<1>();
        __syncthreads();

        unsigned tbase = smb + buf * STG;
        #pragma unroll
        for (int ks = 0; ks < 2; ks++) {
            unsigned a[4][4];
            #pragma unroll
            for (int i = 0; i < 4; i++)
                ldsm4(tbase + aLd + ks * 32 + i * (16 * 80),
                      a[i][0], a[i][1], a[i][2], a[i][3]);
            unsigned b[2][4];
            #pragma unroll
            for (int p = 0; p < 2; p++)
                ldsm4t(tbase + bLd + ks * (16 * 272) + p * 32,
                       b[p][0], b[p][1], b[p][2], b[p][3]);
            #pragma unroll
            for (int i = 0; i < 4; i++)
                #pragma unroll
                for (int jc = 0; jc < 4; jc++)
                    mma16816(acc[i][jc],
                             a[i][0], a[i][1], a[i][2], a[i][3],
                             b[jc >> 1][(jc & 1) * 2], b[jc >> 1][(jc & 1) * 2 + 1]);
        }

        if (s + 2 < S) {
            int nb = buf + 2; if (nb >= 3) nb -= 3;
            int k0 = (s + 2) * 32;
            unsigned base = smb + nb * STG;
            cp16(base + aDst[0], aptr[0] + k0);
            cp16(base + aDst[1], aptr[1] + k0);
            cp16(base + bDst[0], bptr + (long)(s + 2) * bStep);
            cp16(base + bDst[1], bptr + (long)(s + 2) * bStep + bOff2);
            cp_commit();
        }
        buf++; if (buf >= 3) buf -= 3;
    }

    // ---------------- register-direct epilogue ----------------
    int gr = lane >> 2;          // 0..7
    int gc = (lane & 3) * 2;     // 0,2,4,6

    if (EPI == 2) {
        #pragma unroll
        for (int i = 0; i < 4; i++) {
            int r0 = m0 + wm * 64 + i * 16 + gr;
            #pragma unroll
            for (int jc = 0; jc < 4; jc++) {
                int col = n0 + wn * 32 + jc * 8 + gc;
                *(float2*)(outF + (size_t)r0 * ldF + col) =
                    make_float2(acc[i][jc][0], acc[i][jc][1]);
                *(float2*)(outF + (size_t)(r0 + 8) * ldF + col) =
                    make_float2(acc[i][jc][2], acc[i][jc][3]);
            }
        }
    } else if (EPI == 0) {
        #pragma unroll
        for (int i = 0; i < 4; i++) {
            int ml0 = m0 + wm * 64 + i * 16 + gr;
            int ml1 = ml0 + 8;
            bool v0 = ml0 < Mrows, v1 = ml1 < Mrows;
            #pragma unroll
            for (int jc = 0; jc < 4; jc++) {
                int hcol = (n0 >> 1) + wn * 16 + jc * 4 + (lane & 3);
                if (v0)
                    outH[(size_t)(rbase + ml0) * ldH + hcol] =
                        __float2half_rn(silu_f(acc[i][jc][0]) * acc[i][jc][1]);
                if (v1)
                    outH[(size_t)(rbase + ml1) * ldH + hcol] =
                        __float2half_rn(silu_f(acc[i][jc][2]) * acc[i][jc][3]);
            }
        }
    } else {
        #pragma unroll
        for (int i = 0; i < 4; i++) {
            int ml0 = m0 + wm * 64 + i * 16 + gr;
            int ml1 = ml0 + 8;
            bool v0 = ml0 < Mrows, v1 = ml1 < Mrows;
            float s0 = v0 ? (2.5f * g_bucket_w[e * TT + ml0]) : 0.0f;
            float s1 = v1 ? (2.5f * g_bucket_w[e * TT + ml1]) : 0.0f;
            #pragma unroll
            for (int jc = 0; jc < 4; jc++) {
                int col = n0 + wn * 32 + jc * 8 + gc;
                if (v0) {
                    __half2 h = __floats2half2_rn(acc[i][jc][0] * s0, acc[i][jc][1] * s0);
                    *(__half2*)(outH + (size_t)(rbase + ml0) * ldH + col) = h;
                }
                if (v1) {
                    __half2 h = __floats2half2_rn(acc[i][jc][2] * s1, acc[i][jc][3] * s1);
                    *(__half2*)(outH + (size_t)(rbase + ml1) * ldH + col) = h;
                }
            }
        }
    }
}

// ---------------- combine: out[t] = shared[t] + sum_k y_h[row_k] ----------------
__global__ __launch_bounds__(256) void combine_kernel(float* __restrict__ out) {
    int t = blockIdx.x;
    int rows[TOPK];
    #pragma unroll
    for (int k = 0; k < TOPK; k++) {
        int e = g_slot_e[t * TOPK + k];
        rows[k] = g_rowOff[e] + g_slot_pos[t * TOPK + k];
    }
    int c = threadIdx.x * 4;
    #pragma unroll
    for (int rep = 0; rep < 2; rep++, c += 1024) {
        float4 s = *(float4*)(out + (size_t)t * HH + c);
        #pragma unroll
        for (int k = 0; k < TOPK; k++) {
            uint2 raw = *(const uint2*)(g_y_h + (size_t)rows[k] * HH + c);
            __half2 h0 = *(__half2*)&raw.x;
            __half2 h1 = *(__half2*)&raw.y;
            float2 f0 = __half22float2(h0);
            float2 f1 = __half22float2(h1);
            s.x += f0.x; s.y += f0.y; s.z += f1.x; s.w += f1.y;
        }
        *(float4*)(out + (size_t)t * HH + c) = s;
    }
}

// ---------------- launch ----------------
extern "C" void kernel_launch(void* const* d_in, const int* in_sizes, int n_in,
                              void* d_out, int out_size)
{
    const float* hidden = (const float*)d_in[0];
    const float* gate_w = (const float*)d_in[1];
    const float* gate_b = (const float*)d_in[2];
    const float* w_gu   = (const float*)d_in[3];
    const float* w_dn   = (const float*)d_in[4];
    const float* s_gu   = (const float*)d_in[5];
    const float* s_dn   = (const float*)d_in[6];
    float* out = (float*)d_out;

    __half *x_h, *wgu_p, *wdn_h, *sgu_p, *sdn_h, *h_r, *h_s, *y_h;
    cudaGetSymbolAddress((void**)&x_h,   g_x_h);
    cudaGetSymbolAddress((void**)&wgu_p, g_wgu_p);
    cudaGetSymbolAddress((void**)&wdn_h, g_wdn_h);
    cudaGetSymbolAddress((void**)&sgu_p, g_sgu_p);
    cudaGetSymbolAddress((void**)&sdn_h, g_sdn_h);
    cudaGetSymbolAddress((void**)&h_r,   g_h_r);
    cudaGetSymbolAddress((void**)&h_s,   g_h_s);
    cudaGetSymbolAddress((void**)&y_h,   g_y_h);

    cudaFuncSetAttribute(mm2_kernel<0, true,  true >, cudaFuncAttributeMaxDynamicSharedMemorySize, DYN_SMEM);
    cudaFuncSetAttribute(mm2_kernel<0, false, false>, cudaFuncAttributeMaxDynamicSharedMemorySize, DYN_SMEM);
    cudaFuncSetAttribute(mm2_kernel<1, true,  false>, cudaFuncAttributeMaxDynamicSharedMemorySize, DYN_SMEM);
    cudaFuncSetAttribute(mm2_kernel<2, false, false>, cudaFuncAttributeMaxDynamicSharedMemorySize, DYN_SMEM);

    const int CB = 1184;
    f2h_kernel<<<CB, 256>>>((const float4*)hidden, x_h,   (long)TT * HH / 4);
    pair_kernel<<<CB, 256>>>(w_gu, wgu_p, (long)EE * HH, II);
    pair_kernel<<<CB, 256>>>(s_gu, sgu_p, (long)HH, SIc);
    f2h_kernel<<<CB, 256>>>((const float4*)w_dn, wdn_h, (long)EE * II * HH / 4);
    f2h_kernel<<<CB, 256>>>((const float4*)s_dn, sdn_h, (long)SIc * HH / 4);

    router_gemm_kernel<<<TT / 32, 256>>>(hidden, gate_w);  // also zeroes g_cnt
    topk_kernel<<<TT / 64, 64>>>(gate_b);
    prefix_kernel<<<1, 32>>>();

    // routed GEMM1 + fused act: h_r = silu_pair(gather(X) @ Wgu_p[e])
    mm2_kernel<0, true, true><<<dim3(MAXTILES, NGU / 128), 256, DYN_SMEM>>>(
        x_h, wgu_p, (size_t)HH * NGU, HH, NGU, 0, h_r, II, nullptr, 0);

    // shared GEMM1 + fused act: h_s = silu_pair(X @ Sgu_p)
    mm2_kernel<0, false, false><<<dim3(TT / 128, NGUS / 128), 256, DYN_SMEM>>>(
        x_h, sgu_p, 0, HH, NGUS, TT, h_s, SIc, nullptr, 0);

    // shared GEMM2: out = h_s @ Sdn  (direct register store, initializes all of d_out)
    mm2_kernel<2, false, false><<<dim3(TT / 128, HH / 128), 256, DYN_SMEM>>>(
        h_s, sdn_h, 0, SIc, HH, TT, nullptr, 0, out, HH);

    // routed GEMM2: y_h = 2.5*w * (h_r @ Wdn[e])  (fp16 half2 stores)
    mm2_kernel<1, true, false><<<dim3(MAXTILES, HH / 128), 256, DYN_SMEM>>>(
        h_r, wdn_h, (size_t)II * HH, II, HH, 0, y_h, HH, nullptr, 0);

    // combine routed into d_out
    combine_kernel<<<TT, 256>>>(out);
}